// round 11
// baseline (speedup 1.0000x reference)
#include <cuda_runtime.h>

// LineGraphic2d: 8192x8192 fp32 canvas, 6px-wide capsule nonzero (0.06%).
// R11: persistent grid (1184 CTAs = ~1 wave on 148 SMs), each CTA strides
// over rows -> no wave transitions, segment setup amortized across ~7 rows.
// Store path: 8-px clusters, st.global.cs.v8.f32 (STG.256).
// Mask bit-exact vs XLA ref: unfused fp32 + div.full.f32, e2 < 9 (== dist<3).

#define H 8192
#define W 8192
#define EPSILON_F 0.001f
#define PERSISTENT_BLOCKS 1184   // 148 SMs x 8 CTAs (256 thr, 28 regs -> occ 8)

__device__ __forceinline__ float div_full(float a, float b) {
    float r;
    asm("div.full.f32 %0, %1, %2;" : "=f"(r) : "f"(a), "f"(b));
    return r;
}

__device__ __forceinline__ void stg_cs_256(float* p, const float* v) {
    asm volatile("st.global.cs.v8.f32 [%0], {%1, %2, %3, %4, %5, %6, %7, %8};"
                 :: "l"(p), "f"(v[0]), "f"(v[1]), "f"(v[2]), "f"(v[3]),
                            "f"(v[4]), "f"(v[5]), "f"(v[6]), "f"(v[7])
                 : "memory");
}

__global__ void __launch_bounds__(256) line2d_kernel(
    const float* __restrict__ kp, float* __restrict__ out)
{
    const int tid = threadIdx.x;

    // key_points [2,2]: rows=(p0,p1), cols=(y,x). x8192 = power-of-two: exact,
    // so p0, d match the reference's fp32 scalars bit-for-bit.
    const float4 k = *reinterpret_cast<const float4*>(kp);
    const float p0y = __fmul_rn(k.x, (float)H);
    const float p0x = __fmul_rn(k.y, (float)W);
    const float dy  = __fsub_rn(__fmul_rn(k.z, (float)H), p0y);
    const float dx  = __fsub_rn(__fmul_rn(k.w, (float)W), p0x);
    const float len2 = __fadd_rn(__fmul_rn(dy, dy), __fmul_rn(dx, dx));   // ref rounding
    const float inv_len2 = __frcp_rn(len2);
    const float inv_maxd = __frcp_rn(__fsqrt_rn(134217728.0f));           // 1/norm([8192,8192])

    // Persistent: each CTA owns rows y, y+grid, ... (one wave, no transitions)
    for (int y = blockIdx.x; y < H; y += PERSISTENT_BLOCKS) {
        const float ry = __fsub_rn((float)y, p0y);
        const float ry_dy = __fmul_rn(ry, dy);          // ref's per-row product

        #pragma unroll
        for (int q = 0; q < 4; ++q) {
            const int v8 = (y << 10) + (q << 8) + tid;  // float8 index; warp: 1KB contig
            const int x = (v8 << 3) & (W - 1);          // cluster start pixel

            // ---- one fast midpoint test per 8-px cluster ----
            const float rxm = ((float)x + 3.5f) - p0x;
            float tm = __fmaf_rn(rxm, dx, ry_dy) * inv_len2;
            tm = fminf(fmaxf(tm, 0.0f), 1.0f);
            const float eym = __fmaf_rn(-tm, dy, ry);
            const float exm = __fmaf_rn(-tm, dx, rxm);
            const float e2m = __fmaf_rn(eym, eym, exm * exm);

            float o[8] = {0.f, 0.f, 0.f, 0.f, 0.f, 0.f, 0.f, 0.f};
            if (e2m < 56.25f) {   // dist_mid < 7.5 = 3 + 3.5 (cluster) + 1 (margin)
                #pragma unroll
                for (int j = 0; j < 8; ++j) {
                    // bit-exact ref chain: unfused fp32 + div.full.f32
                    const float rx = __fsub_rn((float)(x + j), p0x);
                    float t = div_full(__fadd_rn(ry_dy, __fmul_rn(rx, dx)), len2);
                    t = fminf(fmaxf(t, 0.0f), 1.0f);
                    const float ey = __fsub_rn(ry, __fmul_rn(t, dy));
                    const float ex = __fsub_rn(rx, __fmul_rn(t, dx));
                    const float e2 = fmaxf(__fadd_rn(__fmul_rn(ey, ey), __fmul_rn(ex, ex)), 1e-12f);
                    // mask: dist<3 <=> e2<9 (sqrt.rn monotone, 9 exact)
                    const float dist = __fsqrt_rn(e2);
                    const float v = 1.0f - __fmaf_rn(dist, inv_maxd, EPSILON_F);
                    o[j] = (e2 < 9.0f) ? v : 0.0f;
                }
            }
            stg_cs_256(out + ((size_t)v8 << 3), o);     // STG.256, 32B-aligned
        }
    }
}

extern "C" void kernel_launch(void* const* d_in, const int* in_sizes, int n_in,
                              void* d_out, int out_size)
{
    const float* kp = (const float*)d_in[0];
    float* out = (float*)d_out;
    line2d_kernel<<<PERSISTENT_BLOCKS, 256>>>(kp, out);
}

// round 12
// speedup vs baseline: 1.1500x; 1.1500x over previous
#include <cuda_runtime.h>

// LineGraphic2d: 8192x8192 fp32 canvas, 6px-wide capsule nonzero (0.06%).
// FINAL (R10 config, re-verified): one row per CTA, 8-px clusters, STG.256
// streaming stores. One midpoint point-to-segment test per cluster; band
// clusters (~0.12%) run the bit-exact XLA chain (unfused fp32 + div.full.f32,
// mask e2 < 9 == dist < 3 via monotone correctly-rounded sqrt).
// Store-bound at ~6.8 TB/s effective (~85% of HBM spec) — at the write wall:
// three different store schemes all land 41.0±0.1us; compute pipes <25%.

#define H 8192
#define W 8192
#define EPSILON_F 0.001f

__device__ __forceinline__ float div_full(float a, float b) {
    float r;
    asm("div.full.f32 %0, %1, %2;" : "=f"(r) : "f"(a), "f"(b));
    return r;
}

__device__ __forceinline__ void stg_cs_256(float* p, const float* v) {
    asm volatile("st.global.cs.v8.f32 [%0], {%1, %2, %3, %4, %5, %6, %7, %8};"
                 :: "l"(p), "f"(v[0]), "f"(v[1]), "f"(v[2]), "f"(v[3]),
                            "f"(v[4]), "f"(v[5]), "f"(v[6]), "f"(v[7])
                 : "memory");
}

__global__ void __launch_bounds__(256) line2d_kernel(
    const float* __restrict__ kp, float* __restrict__ out)
{
    // One full row per block: 8192 px = 1024 float8 = 256 threads x 4.
    const int y = blockIdx.x;
    const int tid = threadIdx.x;

    // key_points [2,2]: rows=(p0,p1), cols=(y,x). x8192 = power-of-two: exact,
    // so p0, d match the reference's fp32 scalars bit-for-bit.
    const float4 k = *reinterpret_cast<const float4*>(kp);
    const float p0y = __fmul_rn(k.x, (float)H);
    const float p0x = __fmul_rn(k.y, (float)W);
    const float dy  = __fsub_rn(__fmul_rn(k.z, (float)H), p0y);
    const float dx  = __fsub_rn(__fmul_rn(k.w, (float)W), p0x);
    const float len2 = __fadd_rn(__fmul_rn(dy, dy), __fmul_rn(dx, dx));   // ref rounding
    const float inv_len2 = __frcp_rn(len2);
    const float inv_maxd = __frcp_rn(__fsqrt_rn(134217728.0f));           // 1/norm([8192,8192])

    const float ry = __fsub_rn((float)y, p0y);
    const float ry_dy = __fmul_rn(ry, dy);              // ref's per-row product

    #pragma unroll
    for (int q = 0; q < 4; ++q) {
        const int v8 = (y << 10) + (q << 8) + tid;      // float8 index; warp: 1KB contig
        const int x = (v8 << 3) & (W - 1);              // cluster start pixel

        // ---- one fast midpoint test per 8-px cluster ----
        const float rxm = ((float)x + 3.5f) - p0x;
        float tm = __fmaf_rn(rxm, dx, ry_dy) * inv_len2;
        tm = fminf(fmaxf(tm, 0.0f), 1.0f);
        const float eym = __fmaf_rn(-tm, dy, ry);
        const float exm = __fmaf_rn(-tm, dx, rxm);
        const float e2m = __fmaf_rn(eym, eym, exm * exm);

        float o[8] = {0.f, 0.f, 0.f, 0.f, 0.f, 0.f, 0.f, 0.f};
        if (e2m < 56.25f) {   // dist_mid < 7.5 = 3 + 3.5 (cluster radius) + 1 (margin)
            #pragma unroll
            for (int j = 0; j < 8; ++j) {
                // bit-exact ref chain: unfused fp32 + div.full.f32
                const float rx = __fsub_rn((float)(x + j), p0x);
                float t = div_full(__fadd_rn(ry_dy, __fmul_rn(rx, dx)), len2);
                t = fminf(fmaxf(t, 0.0f), 1.0f);
                const float ey = __fsub_rn(ry, __fmul_rn(t, dy));
                const float ex = __fsub_rn(rx, __fmul_rn(t, dx));
                const float e2 = fmaxf(__fadd_rn(__fmul_rn(ey, ey), __fmul_rn(ex, ex)), 1e-12f);
                // mask: dist<3 <=> e2<9 (sqrt.rn monotone, 9 exact)
                const float dist = __fsqrt_rn(e2);
                const float v = 1.0f - __fmaf_rn(dist, inv_maxd, EPSILON_F);
                o[j] = (e2 < 9.0f) ? v : 0.0f;
            }
        }
        stg_cs_256(out + ((size_t)v8 << 3), o);   // STG.256, 32B-aligned
    }
}

extern "C" void kernel_launch(void* const* d_in, const int* in_sizes, int n_in,
                              void* d_out, int out_size)
{
    const float* kp = (const float*)d_in[0];
    float* out = (float*)d_out;
    line2d_kernel<<<H, 256>>>(kp, out);     // one block per row
}